// round 5
// baseline (speedup 1.0000x reference)
#include <cuda_runtime.h>
#include <cstdint>

// GroupGMM: y = concat(pi_logits[16], mu[512], softplus(sigma[512])+1e-7)
// Reformulated as one GEMM:  A[8192 x 16384] @ Wcat[16384 x 1040]
//   A[b, g*512+i] = g[b,g] * x[b,i]   (generated on the fly)
//   column n of Wcat is strided: elem(k,n) = colptr_n[k * On]
// Bias folded in as one extra K-tile (A rows = g, W rows = bias).

#define BM 128
#define BN 128
#define BK 32

__device__ __forceinline__ uint32_t f2tf32(float f) {
    uint32_t u;
    asm("cvt.rna.tf32.f32 %0, %1;" : "=r"(u) : "f"(f));
    return u;
}

__device__ __forceinline__ void mma_tf32(float* d, const uint32_t* a, const uint32_t* b) {
    asm volatile(
        "mma.sync.aligned.m16n8k8.row.col.f32.tf32.tf32.f32 "
        "{%0,%1,%2,%3}, {%4,%5,%6,%7}, {%8,%9}, {%0,%1,%2,%3};\n"
        : "+f"(d[0]), "+f"(d[1]), "+f"(d[2]), "+f"(d[3])
        : "r"(a[0]), "r"(a[1]), "r"(a[2]), "r"(a[3]), "r"(b[0]), "r"(b[1]));
}

__device__ __forceinline__ float softplus_eps(float z) {
    return fmaxf(z, 0.0f) + log1pf(__expf(-fabsf(z))) + 1e-7f;
}

// SMEM layout (floats):
//   xs : 2 * 128 * 36   (x chunk, double buffered by i_chunk parity)
//   gs : 128 * 36       (g block for this M-tile, also the bias-tile A source)
//   ws : 2 * 32 * 136   (tf32-rounded W tile, double buffered) -- stored as u32
#define XS_STRIDE 36
#define WS_STRIDE 136
#define XS_FLOATS (2 * 128 * XS_STRIDE)
#define GS_FLOATS (128 * XS_STRIDE)
#define WS_WORDS  (2 * BK * WS_STRIDE)
#define SMEM_BYTES ((XS_FLOATS + GS_FLOATS + WS_WORDS) * 4)

__global__ __launch_bounds__(256, 1)
void groupgmm_kernel(const float* __restrict__ x,    // [8192,512]
                     const float* __restrict__ gmat, // [8192,32]
                     const float* __restrict__ W_mu, const float* __restrict__ b_mu,
                     const float* __restrict__ W_si, const float* __restrict__ b_si,
                     const float* __restrict__ W_pi, const float* __restrict__ b_pi,
                     float* __restrict__ out)        // [8192,1040]
{
    constexpr int I = 512, G = 32, NTOT = 1040, KTILES = 512; // + 1 bias tile

    extern __shared__ float smem[];
    float*    xs   = smem;
    float*    gs   = smem + XS_FLOATS;
    uint32_t* ws_u = reinterpret_cast<uint32_t*>(smem + XS_FLOATS + GS_FLOATS);

    const int tid   = threadIdx.x;
    const int lane  = tid & 31;
    const int warp  = tid >> 5;
    const int warpM = warp & 3;   // 4 warps along M (32 rows each)
    const int warpN = warp >> 2;  // 2 warps along N (64 cols each)
    const int m0    = blockIdx.y * BM;
    const int n0    = blockIdx.x * BN;

    // -------- per-thread fixed column descriptor (n = n0 + tid%128) --------
    const int nl = tid & 127;
    const int ncl = (n0 + nl < NTOT) ? (n0 + nl) : (NTOT - 1);
    const float *wp, *bp;
    int On;
    if (ncl < 16)       { wp = W_pi + ncl;         bp = b_pi + ncl;         On = 16;  }
    else if (ncl < 528) { wp = W_mu + (ncl - 16);  bp = b_mu + (ncl - 16);  On = 512; }
    else                { wp = W_si + (ncl - 528); bp = b_si + (ncl - 528); On = 512; }
    const int krow0 = tid >> 7;  // 0 or 1

    // -------- load g block [128 x 32] into gs --------
#pragma unroll
    for (int j = 0; j < 4; ++j) {
        int slot = tid + 256 * j;               // 1024 float4 slots
        int r = slot >> 3, c4 = (slot & 7) * 4; // 8 float4 per row of 32
        float4 v = *reinterpret_cast<const float4*>(gmat + (size_t)(m0 + r) * G + c4);
        *reinterpret_cast<float4*>(gs + r * XS_STRIDE + c4) = v;
    }

    // -------- x chunk loader --------
    auto load_x = [&](int ic, int xb) {
#pragma unroll
        for (int j = 0; j < 4; ++j) {
            int slot = tid + 256 * j;
            int r = slot >> 3, c4 = (slot & 7) * 4;
            float4 v = *reinterpret_cast<const float4*>(
                x + (size_t)(m0 + r) * I + ic * BK + c4);
            *reinterpret_cast<float4*>(xs + xb * (128 * XS_STRIDE) + r * XS_STRIDE + c4) = v;
        }
    };

    // -------- W tile global prefetch into registers --------
    float wreg[16];
    auto load_w = [&](int kt) {
        const float* base;
        if (kt == KTILES) {
            base = bp + krow0 * On;                          // bias rows 0..31
        } else {
            int ic = kt >> 5, gg = kt & 31;                  // K order: (i_chunk, group)
            base = wp + (gg * I + ic * BK + krow0) * On;
        }
#pragma unroll
        for (int p = 0; p < 16; ++p)
            wreg[p] = base[(2 * p) * On];
    };
    auto store_w = [&](int buf) {
#pragma unroll
        for (int p = 0; p < 16; ++p)
            ws_u[buf * (BK * WS_STRIDE) + (krow0 + 2 * p) * WS_STRIDE + nl] = f2tf32(wreg[p]);
    };

    // -------- prologue --------
    load_w(0);
    load_x(0, 0);
    store_w(0);
    __syncthreads();

    float acc[2][8][4];
#pragma unroll
    for (int a = 0; a < 2; ++a)
#pragma unroll
        for (int b = 0; b < 8; ++b)
#pragma unroll
            for (int c = 0; c < 4; ++c) acc[a][b][c] = 0.0f;

    // -------- main loop: 512 GEMM K-tiles + 1 bias K-tile --------
    for (int kt = 0; kt <= KTILES; ++kt) {
        const int buf = kt & 1;
        if (kt < KTILES) load_w(kt + 1);  // prefetch next tile (L2 hits)

        const bool bias = (kt == KTILES);
        const int  gg   = kt & 31;
        const float* asrc = bias ? gs : (xs + ((kt >> 5) & 1) * (128 * XS_STRIDE));

        // per-row g multipliers (constant across the 32-wide K-tile)
        float gv[2][2];
        if (bias) {
            gv[0][0] = gv[0][1] = gv[1][0] = gv[1][1] = 1.0f;
        } else {
#pragma unroll
            for (int ms = 0; ms < 2; ++ms) {
                int r = warpM * 32 + ms * 16 + (lane >> 2);
                gv[ms][0] = gs[r * XS_STRIDE + gg];
                gv[ms][1] = gs[(r + 8) * XS_STRIDE + gg];
            }
        }

        const uint32_t* wsb = ws_u + buf * (BK * WS_STRIDE);
#pragma unroll
        for (int ks = 0; ks < 4; ++ks) {
            const int tk = ks * 8 + (lane & 3);
            uint32_t aU[2][4], bU[8][2];
#pragma unroll
            for (int ms = 0; ms < 2; ++ms) {
                int r = warpM * 32 + ms * 16 + (lane >> 2);
                float a0 = asrc[r * XS_STRIDE + tk]           * gv[ms][0];
                float a1 = asrc[(r + 8) * XS_STRIDE + tk]     * gv[ms][1];
                float a2 = asrc[r * XS_STRIDE + tk + 4]       * gv[ms][0];
                float a3 = asrc[(r + 8) * XS_STRIDE + tk + 4] * gv[ms][1];
                aU[ms][0] = f2tf32(a0);
                aU[ms][1] = f2tf32(a1);
                aU[ms][2] = f2tf32(a2);
                aU[ms][3] = f2tf32(a3);
            }
#pragma unroll
            for (int ns = 0; ns < 8; ++ns) {
                int cb = warpN * 64 + ns * 8 + (lane >> 2);
                bU[ns][0] = wsb[(ks * 8 + (lane & 3)) * WS_STRIDE + cb];
                bU[ns][1] = wsb[(ks * 8 + (lane & 3) + 4) * WS_STRIDE + cb];
            }
#pragma unroll
            for (int ms = 0; ms < 2; ++ms)
#pragma unroll
                for (int ns = 0; ns < 8; ++ns)
                    mma_tf32(acc[ms][ns], aU[ms], bU[ns]);
        }

        if (kt < KTILES) {
            // refill the *other* x parity buffer when the i_chunk advances
            if (((kt + 1) & 31) == 0 && (kt + 1) < KTILES) {
                int icn = (kt + 1) >> 5;
                load_x(icn, icn & 1);
            }
            store_w(buf ^ 1);
            __syncthreads();
        }
    }

    // -------- epilogue: activation + store --------
#pragma unroll
    for (int ms = 0; ms < 2; ++ms) {
#pragma unroll
        for (int ns = 0; ns < 8; ++ns) {
            int r0 = m0 + warpM * 32 + ms * 16 + (lane >> 2);
            int c0 = n0 + warpN * 64 + ns * 8 + (lane & 3) * 2;
            if (c0 < NTOT) {
                bool sig = (c0 >= 528);
                float v0 = acc[ms][ns][0], v1 = acc[ms][ns][1];
                float v2 = acc[ms][ns][2], v3 = acc[ms][ns][3];
                if (sig) {
                    v0 = softplus_eps(v0); v1 = softplus_eps(v1);
                    v2 = softplus_eps(v2); v3 = softplus_eps(v3);
                }
                *reinterpret_cast<float2*>(out + (size_t)r0 * NTOT + c0)       = make_float2(v0, v1);
                *reinterpret_cast<float2*>(out + (size_t)(r0 + 8) * NTOT + c0) = make_float2(v2, v3);
            }
        }
    }
}

extern "C" void kernel_launch(void* const* d_in, const int* in_sizes, int n_in,
                              void* d_out, int out_size) {
    const float* x    = (const float*)d_in[0];
    const float* g    = (const float*)d_in[1];
    const float* W_mu = (const float*)d_in[2];
    const float* b_mu = (const float*)d_in[3];
    const float* W_si = (const float*)d_in[4];
    const float* b_si = (const float*)d_in[5];
    const float* W_pi = (const float*)d_in[6];
    const float* b_pi = (const float*)d_in[7];
    float* out = (float*)d_out;

    cudaFuncSetAttribute(groupgmm_kernel,
                         cudaFuncAttributeMaxDynamicSharedMemorySize, SMEM_BYTES);

    dim3 grid((1040 + BN - 1) / BN, 8192 / BM);  // (9, 64)
    groupgmm_kernel<<<grid, 256, SMEM_BYTES>>>(x, g, W_mu, b_mu, W_si, b_si,
                                               W_pi, b_pi, out);
}

// round 11
// speedup vs baseline: 1.0431x; 1.0431x over previous
#include <cuda_runtime.h>
#include <cstdint>

// GroupGMM as one GEMM on mma.sync bf16 (m16n8k16, fp32 accum):
//   D[8192 x 1040] = A[8192 x 16384] @ Wcat[16384 x 1040]
//   K order = (i_chunk outer, group inner); A[b, ·] = g[b,gg] * x[b, ic*32+k]
//   built in registers; bias folded as the final K-tile (A = g, B = bias).

#define THREADS 512

namespace {
constexpr int BM = 256, BN = 64, BK = 32;
constexpr int IDIM = 512, GDIM = 32, NTOT = 1040;
constexpr int KTILES = 512;          // GEMM tiles; index KTILES = bias tile

// smem layout (float offsets)
constexpr int XS = 0;                 // x chunk  [256][36]
constexpr int GS = 256 * 36;          // g block  [256][36]
constexpr int BF = 2 * 256 * 36;      // B frags  u32 [2 buf][2 wN][2 ks][32 lane][12]
constexpr int SMEM_FLOATS = BF + 2 * 2 * 2 * 32 * 12;
constexpr int SMEM_BYTES  = SMEM_FLOATS * 4;   // 86016 B
}  // namespace

__device__ __forceinline__ uint32_t pack_bf16(float lo, float hi) {
    uint32_t r;
    asm("cvt.rn.bf16x2.f32 %0, %1, %2;" : "=r"(r) : "f"(hi), "f"(lo));
    return r;
}
__device__ __forceinline__ void mma_bf16(float* d, const uint32_t* a, const uint32_t* b) {
    asm volatile(
        "mma.sync.aligned.m16n8k16.row.col.f32.bf16.bf16.f32 "
        "{%0,%1,%2,%3}, {%4,%5,%6,%7}, {%8,%9}, {%0,%1,%2,%3};\n"
        : "+f"(d[0]), "+f"(d[1]), "+f"(d[2]), "+f"(d[3])
        : "r"(a[0]), "r"(a[1]), "r"(a[2]), "r"(a[3]), "r"(b[0]), "r"(b[1]));
}
__device__ __forceinline__ float softplus_eps(float z) {
    return fmaxf(z, 0.0f) + log1pf(__expf(-fabsf(z))) + 1e-7f;
}

__global__ __launch_bounds__(THREADS, 1)
void groupgmm_bf16(const float* __restrict__ x,    // [8192,512]
                   const float* __restrict__ gmat, // [8192,32]
                   const float* __restrict__ W_mu, const float* __restrict__ b_mu,
                   const float* __restrict__ W_si, const float* __restrict__ b_si,
                   const float* __restrict__ W_pi, const float* __restrict__ b_pi,
                   float* __restrict__ out)        // [8192,1040]
{
    extern __shared__ float sm[];
    float*    xs = sm + XS;
    float*    gs = sm + GS;
    uint32_t* bf = reinterpret_cast<uint32_t*>(sm + BF);

    const int tid   = threadIdx.x;
    const int lane  = tid & 31;
    const int warp  = tid >> 5;
    const int warpM = warp & 7;    // 8 warps along M (32 rows each)
    const int warpN = warp >> 3;   // 2 warps along N (32 cols each)
    const int m0 = blockIdx.y * BM;
    const int n0 = blockIdx.x * BN;

    // -------- producer role: column nl, k-rows kh*4..kh*4+3 --------
    const int nl = tid & 63;
    const int kh = tid >> 6;                 // 0..7
    int nc = n0 + nl; if (nc >= NTOT) nc = NTOT - 1;
    const float *wp, *bp; int On;
    if (nc < 16)       { wp = W_pi + nc;         bp = b_pi + nc;         On = 16;  }
    else if (nc < 528) { wp = W_mu + (nc - 16);  bp = b_mu + (nc - 16);  On = 512; }
    else               { wp = W_si + (nc - 528); bp = b_si + (nc - 528); On = 512; }
    // B-fragment store slots for this thread's two k-pairs
    const int ks_p = kh >> 2;                // k16-step
    const int wNp  = nl >> 5;
    const int nsp  = (nl >> 3) & 3;
    int laneP[2], idxP[2];
#pragma unroll
    for (int s = 0; s < 2; ++s) {
        int u = (kh & 3) * 2 + s;            // pair index within k16 step
        laneP[s] = (nl & 7) * 4 + (u & 3);
        idxP[s]  = nsp * 2 + (u >> 2);
    }

    // -------- consumer row indices: rows R0 + {0,8} for ms = 0,1 --------
    int rowIx[4];
#pragma unroll
    for (int rid = 0; rid < 4; ++rid)
        rowIx[rid] = warpM * 32 + (rid >> 1) * 16 + (rid & 1) * 8 + (lane >> 2);

    // -------- prologue: load g block + x chunk 0 --------
#pragma unroll
    for (int j = 0; j < 4; ++j) {
        int slot = tid + THREADS * j;        // 2048 float4 slots
        int row = slot >> 3, c4 = (slot & 7) * 4;
        *reinterpret_cast<float4*>(gs + row * 36 + c4) =
            *reinterpret_cast<const float4*>(gmat + (size_t)(m0 + row) * GDIM + c4);
        *reinterpret_cast<float4*>(xs + row * 36 + c4) =
            *reinterpret_cast<const float4*>(x + (size_t)(m0 + row) * IDIM + c4);
    }
    __syncthreads();

    // -------- produce tile 0 into buffer 0 --------
    {
        const float* base = wp + (size_t)(kh * 4) * On;   // gg=0, ic=0
        float wv[4];
#pragma unroll
        for (int r = 0; r < 4; ++r) wv[r] = base[(size_t)r * On];
#pragma unroll
        for (int s = 0; s < 2; ++s)
            bf[(((0 * 2 + wNp) * 2 + ks_p) * 32 + laneP[s]) * 12 + idxP[s]] =
                pack_bf16(wv[2 * s], wv[2 * s + 1]);
    }
    __syncthreads();

    float acc[2][4][4];
#pragma unroll
    for (int a = 0; a < 2; ++a)
#pragma unroll
        for (int b = 0; b < 4; ++b)
#pragma unroll
            for (int c = 0; c < 4; ++c) acc[a][b][c] = 0.0f;

    float xr[4][8];   // x fragments: [row][k = 8j + 2c + h], c = lane&3

    // -------- main loop: 512 GEMM tiles + 1 bias tile --------
    for (int t = 0; t <= KTILES; ++t) {
        const int buf = t & 1, nbuf = buf ^ 1;

        // W prefetch for tile t+1 (pure gmem; latency hidden by MMA section)
        float wv[4];
        if (t < KTILES) {
            const float* base;
            const int tp = t + 1;
            if (tp < KTILES) {
                const int gg = tp & 31, ic = tp >> 5;
                base = wp + (size_t)(gg * IDIM + ic * BK + kh * 4) * On;
            } else {
                base = bp + (size_t)(kh * 4) * On;
            }
#pragma unroll
            for (int r = 0; r < 4; ++r) wv[r] = base[(size_t)r * On];
        }

        // refresh x fragments at each i_chunk boundary (bias tile reads g)
        if ((t & 31) == 0) {
            const float* srcb = (t == KTILES) ? gs : xs;
#pragma unroll
            for (int rid = 0; rid < 4; ++rid) {
                const float* rp = srcb + rowIx[rid] * 36 + (lane & 3) * 2;
#pragma unroll
                for (int j = 0; j < 4; ++j) {
                    float2 v = *reinterpret_cast<const float2*>(rp + 8 * j);
                    xr[rid][2 * j] = v.x; xr[rid][2 * j + 1] = v.y;
                }
            }
        }

        // refill xs with the next i_chunk (reads of current chunk finished
        // before last tile's __syncthreads; t=481 excluded -> chunks 1..15)
        if ((t & 31) == 1 && t < 480) {
            const int icn = (t >> 5) + 1;
#pragma unroll
            for (int j = 0; j < 4; ++j) {
                int slot = tid + THREADS * j;
                int row = slot >> 3, c4 = (slot & 7) * 4;
                *reinterpret_cast<float4*>(xs + row * 36 + c4) =
                    *reinterpret_cast<const float4*>(
                        x + (size_t)(m0 + row) * IDIM + icn * BK + c4);
            }
        }

        // per-row g multipliers (constant over the 32-wide K-tile)
        float gv[4];
        if (t < KTILES) {
            const int gg = t & 31;
#pragma unroll
            for (int rid = 0; rid < 4; ++rid) gv[rid] = gs[rowIx[rid] * 36 + gg];
        } else {
#pragma unroll
            for (int rid = 0; rid < 4; ++rid) gv[rid] = 1.0f;
        }

        // build A fragments: 32 FMUL + 16 cvt-packs
        uint32_t aU[2][2][4];   // [ms][k16-step s][4 regs]
#pragma unroll
        for (int ms = 0; ms < 2; ++ms) {
            const int r0 = ms * 2, r1 = ms * 2 + 1;
#pragma unroll
            for (int s = 0; s < 2; ++s) {
                aU[ms][s][0] = pack_bf16(xr[r0][4*s  ] * gv[r0], xr[r0][4*s+1] * gv[r0]);
                aU[ms][s][1] = pack_bf16(xr[r1][4*s  ] * gv[r1], xr[r1][4*s+1] * gv[r1]);
                aU[ms][s][2] = pack_bf16(xr[r0][4*s+2] * gv[r0], xr[r0][4*s+3] * gv[r0]);
                aU[ms][s][3] = pack_bf16(xr[r1][4*s+2] * gv[r1], xr[r1][4*s+3] * gv[r1]);
            }
        }

        // consume tile t: 2 k16-steps x (2 LDS.128 + 8 MMAs)
#pragma unroll
        for (int s = 0; s < 2; ++s) {
            const uint32_t* bb = bf + (((buf * 2 + warpN) * 2 + s) * 32 + lane) * 12;
            uint4 v0 = *reinterpret_cast<const uint4*>(bb);
            uint4 v1 = *reinterpret_cast<const uint4*>(bb + 4);
            uint32_t bU[8] = {v0.x, v0.y, v0.z, v0.w, v1.x, v1.y, v1.z, v1.w};
#pragma unroll
            for (int ms = 0; ms < 2; ++ms)
#pragma unroll
                for (int ns = 0; ns < 4; ++ns)
                    mma_bf16(acc[ms][ns], aU[ms][s], &bU[ns * 2]);
        }

        // produce tile t+1 into the other buffer
        if (t < KTILES) {
#pragma unroll
            for (int s = 0; s < 2; ++s)
                bf[(((nbuf * 2 + wNp) * 2 + ks_p) * 32 + laneP[s]) * 12 + idxP[s]] =
                    pack_bf16(wv[2 * s], wv[2 * s + 1]);
        }

        __syncthreads();
    }

    // -------- epilogue: activation + store --------
#pragma unroll
    for (int ms = 0; ms < 2; ++ms) {
#pragma unroll
        for (int ns = 0; ns < 4; ++ns) {
            const int rA = m0 + warpM * 32 + ms * 16 + (lane >> 2);
            const int c0 = n0 + warpN * 32 + ns * 8 + (lane & 3) * 2;
            if (c0 < NTOT) {
                const bool sig = (c0 >= 528);
                float v0 = acc[ms][ns][0], v1 = acc[ms][ns][1];
                float v2 = acc[ms][ns][2], v3 = acc[ms][ns][3];
                if (sig) {
                    v0 = softplus_eps(v0); v1 = softplus_eps(v1);
                    v2 = softplus_eps(v2); v3 = softplus_eps(v3);
                }
                *reinterpret_cast<float2*>(out + (size_t)rA * NTOT + c0)       = make_float2(v0, v1);
                *reinterpret_cast<float2*>(out + (size_t)(rA + 8) * NTOT + c0) = make_float2(v2, v3);
            }
        }
    }
}

extern "C" void kernel_launch(void* const* d_in, const int* in_sizes, int n_in,
                              void* d_out, int out_size) {
    const float* x    = (const float*)d_in[0];
    const float* g    = (const float*)d_in[1];
    const float* W_mu = (const float*)d_in[2];
    const float* b_mu = (const float*)d_in[3];
    const float* W_si = (const float*)d_in[4];
    const float* b_si = (const float*)d_in[5];
    const float* W_pi = (const float*)d_in[6];
    const float* b_pi = (const float*)d_in[7];
    float* out = (float*)d_out;

    cudaFuncSetAttribute(groupgmm_bf16,
                         cudaFuncAttributeMaxDynamicSharedMemorySize, SMEM_BYTES);

    dim3 grid((NTOT + BN - 1) / BN, 8192 / BM);  // (17, 32) = 544 CTAs
    groupgmm_bf16<<<grid, THREADS, SMEM_BYTES>>>(x, g, W_mu, b_mu, W_si, b_si,
                                                 W_pi, b_pi, out);
}

// round 12
// speedup vs baseline: 1.7733x; 1.7000x over previous
#include <cuda_runtime.h>
#include <cstdint>

// GroupGMM as one GEMM on mma.sync bf16 (m16n8k16, fp32 accum):
//   D[8192 x 1040] = A[8192 x 16384] @ Wcat[16384 x 1040]
//   K order = (i_chunk outer, group inner); A[b,·] = g[b,gg] * x[b, ic*32+k]
//   built in registers; bias folded as K-tile 512 (A = g, B = bias).
// R11: 4-tile sync periods + 8-slot B-fragment ring + conflict-free frag LDS.

#define THREADS 512

namespace {
constexpr int BM = 256, BN = 64, BK = 32;
constexpr int IDIM = 512, GDIM = 32, NTOT = 1040;
constexpr int KTILES = 512;            // GEMM tiles; index 512 = bias tile
constexpr int NPER = 128;              // 4-tile periods

// smem layout (float offsets)
constexpr int XS = 0;                  // x chunk [256][36]
constexpr int GS = 256 * 36;           // g block [256][36]
constexpr int BF = 2 * 256 * 36;       // frag ring (u32): [8 slot][2 wN][2 s][2 h][32 lane][4]
constexpr int SLOT_U32 = 2 * 2 * 2 * 32 * 4;   // 1024 u32 per slot
constexpr int SMEM_FLOATS = BF + 8 * SLOT_U32;
constexpr int SMEM_BYTES  = SMEM_FLOATS * 4;   // 106496 B
}  // namespace

__device__ __forceinline__ uint32_t pack_bf16(float lo, float hi) {
    uint32_t r;
    asm("cvt.rn.bf16x2.f32 %0, %1, %2;" : "=r"(r) : "f"(hi), "f"(lo));
    return r;
}
__device__ __forceinline__ void mma_bf16(float* d, const uint32_t* a, const uint32_t* b) {
    asm volatile(
        "mma.sync.aligned.m16n8k16.row.col.f32.bf16.bf16.f32 "
        "{%0,%1,%2,%3}, {%4,%5,%6,%7}, {%8,%9}, {%0,%1,%2,%3};\n"
        : "+f"(d[0]), "+f"(d[1]), "+f"(d[2]), "+f"(d[3])
        : "r"(a[0]), "r"(a[1]), "r"(a[2]), "r"(a[3]), "r"(b[0]), "r"(b[1]));
}
__device__ __forceinline__ float softplus_eps(float z) {
    return fmaxf(z, 0.0f) + log1pf(__expf(-fabsf(z))) + 1e-7f;
}

__global__ __launch_bounds__(THREADS, 1)
void groupgmm_bf16(const float* __restrict__ x,    // [8192,512]
                   const float* __restrict__ gmat, // [8192,32]
                   const float* __restrict__ W_mu, const float* __restrict__ b_mu,
                   const float* __restrict__ W_si, const float* __restrict__ b_si,
                   const float* __restrict__ W_pi, const float* __restrict__ b_pi,
                   float* __restrict__ out)        // [8192,1040]
{
    extern __shared__ float sm[];
    float*    xs = sm + XS;
    float*    gs = sm + GS;
    uint32_t* bf = reinterpret_cast<uint32_t*>(sm + BF);

    const int tid   = threadIdx.x;
    const int lane  = tid & 31;
    const int warp  = tid >> 5;
    const int warpM = warp & 7;    // 8 warps along M (32 rows each)
    const int warpN = warp >> 3;   // 2 warps along N (32 cols each)
    const int m0 = blockIdx.y * BM;
    const int n0 = blockIdx.x * BN;

    // -------- producer role: column nl, k-rows kh*4 .. kh*4+3 --------
    const int nl = tid & 63;
    const int kh = tid >> 6;                 // 0..7
    int nc = n0 + nl; if (nc >= NTOT) nc = NTOT - 1;
    const float *wp, *bp; int On;
    if (nc < 16)       { wp = W_pi + nc;         bp = b_pi + nc;         On = 16;  }
    else if (nc < 528) { wp = W_mu + (nc - 16);  bp = b_mu + (nc - 16);  On = 512; }
    else               { wp = W_si + (nc - 528); bp = b_si + (nc - 528); On = 512; }
    // fragment store coordinates (conflict-free layout)
    const int sP   = kh >> 2;                // k16 step
    const int regP = (kh >> 1) & 1;          // frag reg (k low/high 8)
    const int wNp  = nl >> 5;
    const int nsP  = (nl >> 3) & 3;
    const int uP   = nsP * 2 + regP;         // 0..7 within lane's 8 frag words
    const int hP   = uP >> 2, posP = uP & 3;
    const int laneP0 = (nl & 7) * 4 + (kh & 1) * 2;   // + p (p = 0,1)
    // u32 index inside a slot for pack p:
    //   ((wNp*2 + sP)*2 + hP)*128 + (laneP0+p)*4 + posP
    const int stBase = ((wNp * 2 + sP) * 2 + hP) * 128 + laneP0 * 4 + posP;

    // -------- consumer row indices --------
    int rowIx[4];
#pragma unroll
    for (int rid = 0; rid < 4; ++rid)
        rowIx[rid] = warpM * 32 + (rid >> 1) * 16 + (rid & 1) * 8 + (lane >> 2);

    // W base for K-tile t (t == KTILES -> bias rows)
    auto wbase = [&](int t) -> const float* {
        return (t < KTILES)
            ? wp + (size_t)((t & 31) * IDIM + (t >> 5) * BK + kh * 4) * On
            : bp + (size_t)(kh * 4) * On;
    };

    // -------- prologue: g block + x chunk 0 --------
#pragma unroll
    for (int j = 0; j < 4; ++j) {
        int slot = tid + THREADS * j;        // 2048 float4 slots
        int row = slot >> 3, c4 = (slot & 7) * 4;
        *reinterpret_cast<float4*>(gs + row * 36 + c4) =
            *reinterpret_cast<const float4*>(gmat + (size_t)(m0 + row) * GDIM + c4);
        *reinterpret_cast<float4*>(xs + row * 36 + c4) =
            *reinterpret_cast<const float4*>(x + (size_t)(m0 + row) * IDIM + c4);
    }

    // -------- produce tiles 0..3 into slots 0..3 --------
    float wv[16];
#pragma unroll
    for (int j = 0; j < 4; ++j) {
        const float* base = wbase(j);
#pragma unroll
        for (int r = 0; r < 4; ++r) wv[j * 4 + r] = base[(size_t)r * On];
    }
#pragma unroll
    for (int j = 0; j < 4; ++j) {
        uint32_t* sl = bf + j * SLOT_U32;
        sl[stBase]     = pack_bf16(wv[j * 4 + 0], wv[j * 4 + 1]);
        sl[stBase + 4] = pack_bf16(wv[j * 4 + 2], wv[j * 4 + 3]);
    }
    __syncthreads();

    float acc[2][4][4];
#pragma unroll
    for (int a = 0; a < 2; ++a)
#pragma unroll
        for (int b = 0; b < 4; ++b)
#pragma unroll
            for (int c = 0; c < 4; ++c) acc[a][b][c] = 0.0f;

    float xr[4][8];   // x fragments: [rowId][k = 8j + 2(lane&3) + h]

    // -------- main loop: 128 periods of 4 tiles --------
    for (int p = 0; p < NPER; ++p) {
        const int T = p * 4;

        // W prefetch for period p+1 (tiles T+4..T+7; tile 512 = bias, >512 skipped)
#pragma unroll
        for (int j = 0; j < 4; ++j) {
            const int t = T + 4 + j;
            if (t <= KTILES) {
                const float* base = wbase(t);
#pragma unroll
                for (int r = 0; r < 4; ++r) wv[j * 4 + r] = base[(size_t)r * On];
            }
        }

        // refresh x fragments at i_chunk boundary (every 8 periods)
        if ((T & 31) == 0) {
#pragma unroll
            for (int rid = 0; rid < 4; ++rid) {
                const float* rp = xs + rowIx[rid] * 36 + (lane & 3) * 2;
#pragma unroll
                for (int j = 0; j < 4; ++j) {
                    float2 v = *reinterpret_cast<const float2*>(rp + 8 * j);
                    xr[rid][2 * j] = v.x; xr[rid][2 * j + 1] = v.y;
                }
            }
        }

        // consume 4 tiles
#pragma unroll
        for (int u = 0; u < 4; ++u) {
            const int t = T + u;
            const int gg = t & 31;
            float gv[4];
#pragma unroll
            for (int rid = 0; rid < 4; ++rid) gv[rid] = gs[rowIx[rid] * 36 + gg];

            const uint32_t* sl = bf + (t & 7) * SLOT_U32 + warpN * 512;
#pragma unroll
            for (int s = 0; s < 2; ++s) {
                // B frags: 2 conflict-free LDS.128
                uint4 v0 = *reinterpret_cast<const uint4*>(sl + s * 256 + lane * 4);
                uint4 v1 = *reinterpret_cast<const uint4*>(sl + s * 256 + 128 + lane * 4);
                uint32_t bU[8] = {v0.x, v0.y, v0.z, v0.w, v1.x, v1.y, v1.z, v1.w};
                // A frags just-in-time
                uint32_t aUs[8];
#pragma unroll
                for (int ms = 0; ms < 2; ++ms) {
                    const int r0 = ms * 2, r1 = ms * 2 + 1;
                    aUs[ms*4+0] = pack_bf16(xr[r0][4*s  ] * gv[r0], xr[r0][4*s+1] * gv[r0]);
                    aUs[ms*4+1] = pack_bf16(xr[r1][4*s  ] * gv[r1], xr[r1][4*s+1] * gv[r1]);
                    aUs[ms*4+2] = pack_bf16(xr[r0][4*s+2] * gv[r0], xr[r0][4*s+3] * gv[r0]);
                    aUs[ms*4+3] = pack_bf16(xr[r1][4*s+2] * gv[r1], xr[r1][4*s+3] * gv[r1]);
                }
#pragma unroll
                for (int ms = 0; ms < 2; ++ms)
#pragma unroll
                    for (int ns = 0; ns < 4; ++ns)
                        mma_bf16(acc[ms][ns], &aUs[ms * 4], &bU[ns * 2]);
            }
        }

        // refill xs with next i_chunk one period after the boundary
        if ((T & 31) == 4 && T < 480) {
            const int icn = (T >> 5) + 1;
#pragma unroll
            for (int j = 0; j < 4; ++j) {
                int slot = tid + THREADS * j;
                int row = slot >> 3, c4 = (slot & 7) * 4;
                *reinterpret_cast<float4*>(xs + row * 36 + c4) =
                    *reinterpret_cast<const float4*>(
                        x + (size_t)(m0 + row) * IDIM + icn * BK + c4);
            }
        }

        // produce period p+1 fragments into the other ring bank
#pragma unroll
        for (int j = 0; j < 4; ++j) {
            const int t = T + 4 + j;
            if (t <= KTILES) {
                uint32_t* sl = bf + (t & 7) * SLOT_U32;
                sl[stBase]     = pack_bf16(wv[j * 4 + 0], wv[j * 4 + 1]);
                sl[stBase + 4] = pack_bf16(wv[j * 4 + 2], wv[j * 4 + 3]);
            }
        }

        __syncthreads();
    }

    // -------- bias tile (t = 512): A = g block, slot 0 --------
    {
#pragma unroll
        for (int rid = 0; rid < 4; ++rid) {
            const float* rp = gs + rowIx[rid] * 36 + (lane & 3) * 2;
#pragma unroll
            for (int j = 0; j < 4; ++j) {
                float2 v = *reinterpret_cast<const float2*>(rp + 8 * j);
                xr[rid][2 * j] = v.x; xr[rid][2 * j + 1] = v.y;
            }
        }
        const uint32_t* sl = bf + 0 * SLOT_U32 + warpN * 512;
#pragma unroll
        for (int s = 0; s < 2; ++s) {
            uint4 v0 = *reinterpret_cast<const uint4*>(sl + s * 256 + lane * 4);
            uint4 v1 = *reinterpret_cast<const uint4*>(sl + s * 256 + 128 + lane * 4);
            uint32_t bU[8] = {v0.x, v0.y, v0.z, v0.w, v1.x, v1.y, v1.z, v1.w};
            uint32_t aUs[8];
#pragma unroll
            for (int ms = 0; ms < 2; ++ms) {
                const int r0 = ms * 2, r1 = ms * 2 + 1;
                aUs[ms*4+0] = pack_bf16(xr[r0][4*s  ], xr[r0][4*s+1]);
                aUs[ms*4+1] = pack_bf16(xr[r1][4*s  ], xr[r1][4*s+1]);
                aUs[ms*4+2] = pack_bf16(xr[r0][4*s+2], xr[r0][4*s+3]);
                aUs[ms*4+3] = pack_bf16(xr[r1][4*s+2], xr[r1][4*s+3]);
            }
#pragma unroll
            for (int ms = 0; ms < 2; ++ms)
#pragma unroll
                for (int ns = 0; ns < 4; ++ns)
                    mma_bf16(acc[ms][ns], &aUs[ms * 4], &bU[ns * 2]);
        }
    }

    // -------- epilogue: activation + store --------
#pragma unroll
    for (int ms = 0; ms < 2; ++ms) {
#pragma unroll
        for (int ns = 0; ns < 4; ++ns) {
            const int rA = m0 + warpM * 32 + ms * 16 + (lane >> 2);
            const int c0 = n0 + warpN * 32 + ns * 8 + (lane & 3) * 2;
            if (c0 < NTOT) {
                const bool sig = (c0 >= 528);
                float v0 = acc[ms][ns][0], v1 = acc[ms][ns][1];
                float v2 = acc[ms][ns][2], v3 = acc[ms][ns][3];
                if (sig) {
                    v0 = softplus_eps(v0); v1 = softplus_eps(v1);
                    v2 = softplus_eps(v2); v3 = softplus_eps(v3);
                }
                *reinterpret_cast<float2*>(out + (size_t)rA * NTOT + c0)       = make_float2(v0, v1);
                *reinterpret_cast<float2*>(out + (size_t)(rA + 8) * NTOT + c0) = make_float2(v2, v3);
            }
        }
    }
}

extern "C" void kernel_launch(void* const* d_in, const int* in_sizes, int n_in,
                              void* d_out, int out_size) {
    const float* x    = (const float*)d_in[0];
    const float* g    = (const float*)d_in[1];
    const float* W_mu = (const float*)d_in[2];
    const float* b_mu = (const float*)d_in[3];
    const float* W_si = (const float*)d_in[4];
    const float* b_si = (const float*)d_in[5];
    const float* W_pi = (const float*)d_in[6];
    const float* b_pi = (const float*)d_in[7];
    float* out = (float*)d_out;

    cudaFuncSetAttribute(groupgmm_bf16,
                         cudaFuncAttributeMaxDynamicSharedMemorySize, SMEM_BYTES);

    dim3 grid((NTOT + BN - 1) / BN, 8192 / BM);  // (17, 32) = 544 CTAs
    groupgmm_bf16<<<grid, THREADS, SMEM_BYTES>>>(x, g, W_mu, b_mu, W_si, b_si,
                                                 W_pi, b_pi, out);
}